// round 13
// baseline (speedup 1.0000x reference)
#include <cuda_runtime.h>
#include <cuda_bf16.h>
#include <cuda_fp16.h>
#include <math.h>
#include <stdint.h>

// Problem constants (fixed shapes)
#define BB   8
#define CC   512
#define NN_  2048
#define RR   (BB * NN_)      // 16384 positions
#define MLPH 2048
#define KH   9
#define PAD  4

// ---------------- scratch (device globals; no allocs allowed) ----------------
__device__ __align__(16) float g_Qt [(size_t)RR * CC];   // raw query (residual)
__device__ __align__(16) float g_X  [(size_t)RR * CC];
__device__ __align__(16) float g_H2 [(size_t)RR * CC];   // X + mlp out (after fusion)

// fp16 activations
__device__ __align__(16) __half g_Qa [(size_t)RR * CC];
__device__ __align__(16) __half g_Ka [(size_t)RR * CC];
__device__ __align__(16) __half g_Va [(size_t)RR * CC];
__device__ __align__(16) __half g_Qpa[(size_t)RR * CC];
__device__ __align__(16) __half g_Kpa[(size_t)RR * CC];
__device__ __align__(16) __half g_Vpa[(size_t)RR * CC];
__device__ __align__(16) __half g_L2a[(size_t)RR * CC];
__device__ __align__(16) __half g_Ha [(size_t)RR * MLPH];

// fp16 weights
__device__ __align__(16) __half g_wq[CC * CC];
__device__ __align__(16) __half g_wk[CC * CC];
__device__ __align__(16) __half g_wv[CC * CC];
__device__ __align__(16) __half g_w1[MLPH * CC];  // w1^T
__device__ __align__(16) __half g_w2[CC * MLPH];  // w2^T

// ---------------- helpers ----------------------------------------------------
__device__ __forceinline__ uint32_t smem_u32(const void* p) {
    uint32_t a;
    asm("{ .reg .u64 t; cvta.to.shared.u64 t, %1; cvt.u32.u64 %0, t; }"
        : "=r"(a) : "l"(p));
    return a;
}
__device__ __forceinline__ void cpa16(uint32_t dst, const void* src) {
    asm volatile("cp.async.cg.shared.global [%0], [%1], 16;"
                 :: "r"(dst), "l"(src) : "memory");
}
#define CP_COMMIT() asm volatile("cp.async.commit_group;" ::: "memory")
#define CP_WAIT(n)  asm volatile("cp.async.wait_group %0;" :: "n"(n) : "memory")

__device__ __forceinline__ void ldsm4(uint32_t& r0, uint32_t& r1,
                                      uint32_t& r2, uint32_t& r3, uint32_t a) {
    asm volatile("ldmatrix.sync.aligned.m8n8.x4.shared.b16 {%0,%1,%2,%3}, [%4];"
                 : "=r"(r0), "=r"(r1), "=r"(r2), "=r"(r3) : "r"(a));
}
__device__ __forceinline__ void mma16816(float* c, uint32_t a0, uint32_t a1,
                                         uint32_t a2, uint32_t a3,
                                         uint32_t b0, uint32_t b1) {
    asm volatile(
        "mma.sync.aligned.m16n8k16.row.col.f32.f16.f16.f32 "
        "{%0,%1,%2,%3}, {%4,%5,%6,%7}, {%8,%9}, {%0,%1,%2,%3};"
        : "+f"(c[0]), "+f"(c[1]), "+f"(c[2]), "+f"(c[3])
        : "r"(a0), "r"(a1), "r"(a2), "r"(a3), "r"(b0), "r"(b1));
}
// smem tile rows of 64 fp16 (128B = 8 x 16B units); unit XOR-swizzled by row&7
__device__ __forceinline__ uint32_t swoff(int row, int kb) {
    return (uint32_t)((row << 7) + ((((kb >> 4) ^ (row & 7))) << 4));
}

// ============================================================================
// K1: fused LN: one pass over inputs. Block = 8 positions x all 512 channels.
// Stages q/qe/k/ke in smem, computes per-position stats (warp butterflies),
// emits fp16 Qa/Ka/Va + fp32 Qt.
// ============================================================================
#define LNF_SMEM (4 * 512 * 9 * 4)   // 73728 B

__global__ __launch_bounds__(256) void k_lnfuse(
    const float* __restrict__ q,  const float* __restrict__ k,
    const float* __restrict__ qe, const float* __restrict__ ke,
    const float* __restrict__ gn, const float* __restrict__ bn)
{
    extern __shared__ float sm[];
    float* sQE = sm;                  // [512][9]
    float* sKE = sm + 512 * 9;
    float* sQ  = sm + 2 * 512 * 9;
    float* sK  = sm + 3 * 512 * 9;

    int b  = blockIdx.y;
    int n0 = blockIdx.x * 8;
    int tid = threadIdx.x;

    // load: 2 channel rows per thread, 8 floats each per array
#pragma unroll
    for (int i = 0; i < 2; i++) {
        int c = tid + i * 256;
        size_t idx = (size_t)b * CC * NN_ + (size_t)c * NN_ + n0;
        float4 q0 = *(const float4*)(q  + idx);
        float4 q1 = *(const float4*)(q  + idx + 4);
        float4 e0 = *(const float4*)(qe + idx);
        float4 e1 = *(const float4*)(qe + idx + 4);
        float4 k0 = *(const float4*)(k  + idx);
        float4 k1 = *(const float4*)(k  + idx + 4);
        float4 f0 = *(const float4*)(ke + idx);
        float4 f1 = *(const float4*)(ke + idx + 4);
        float* dQ  = sQ  + c * 9;
        float* dK  = sK  + c * 9;
        float* dQE = sQE + c * 9;
        float* dKE = sKE + c * 9;
        dQ[0]=q0.x; dQ[1]=q0.y; dQ[2]=q0.z; dQ[3]=q0.w;
        dQ[4]=q1.x; dQ[5]=q1.y; dQ[6]=q1.z; dQ[7]=q1.w;
        dK[0]=k0.x; dK[1]=k0.y; dK[2]=k0.z; dK[3]=k0.w;
        dK[4]=k1.x; dK[5]=k1.y; dK[6]=k1.z; dK[7]=k1.w;
        dQE[0]=q0.x+e0.x; dQE[1]=q0.y+e0.y; dQE[2]=q0.z+e0.z; dQE[3]=q0.w+e0.w;
        dQE[4]=q1.x+e1.x; dQE[5]=q1.y+e1.y; dQE[6]=q1.z+e1.z; dQE[7]=q1.w+e1.w;
        dKE[0]=k0.x+f0.x; dKE[1]=k0.y+f0.y; dKE[2]=k0.z+f0.z; dKE[3]=k0.w+f0.w;
        dKE[4]=k1.x+f1.x; dKE[5]=k1.y+f1.y; dKE[6]=k1.z+f1.z; dKE[7]=k1.w+f1.w;
    }
    __syncthreads();

    int p    = tid >> 5;     // position within block (0..7)
    int lane = tid & 31;

    float qs = 0.f, qss = 0.f, ks = 0.f, kss = 0.f;
#pragma unroll
    for (int j = 0; j < 16; j++) {
        int c = lane + j * 32;
        float qv = sQE[c * 9 + p];
        float kv = sKE[c * 9 + p];
        qs += qv; qss += qv * qv;
        ks += kv; kss += kv * kv;
    }
#pragma unroll
    for (int o = 16; o > 0; o >>= 1) {
        qs  += __shfl_xor_sync(0xffffffffu, qs,  o);
        qss += __shfl_xor_sync(0xffffffffu, qss, o);
        ks  += __shfl_xor_sync(0xffffffffu, ks,  o);
        kss += __shfl_xor_sync(0xffffffffu, kss, o);
    }
    const float invC = 1.0f / CC;
    float qm = qs * invC, km = ks * invC;
    float qrs = rsqrtf(qss * invC - qm * qm + 1e-5f);
    float krs = rsqrtf(kss * invC - km * km + 1e-5f);

    // convert + write: lane covers c = lane*16 .. lane*16+15 for its position
    size_t qb = (size_t)(b * NN_ + n0 + p) * CC;
    int c0 = lane * 16;
    __half2 oq[8], ok[8], ov[8];
    float qt[16];
#pragma unroll
    for (int j = 0; j < 8; j++) {
        int c = c0 + 2 * j;
        float g0 = gn[c], g1 = gn[c + 1];
        float b0 = bn[c], b1 = bn[c + 1];
        float qe0 = sQE[c * 9 + p],      qe1 = sQE[(c + 1) * 9 + p];
        float ke0 = sKE[c * 9 + p],      ke1 = sKE[(c + 1) * 9 + p];
        float kr0 = sK [c * 9 + p],      kr1 = sK [(c + 1) * 9 + p];
        qt[2*j]   = sQ[c * 9 + p];
        qt[2*j+1] = sQ[(c + 1) * 9 + p];
        oq[j] = __floats2half2_rn((qe0 - qm) * qrs * g0 + b0,
                                  (qe1 - qm) * qrs * g1 + b1);
        ok[j] = __floats2half2_rn((ke0 - km) * krs * g0 + b0,
                                  (ke1 - km) * krs * g1 + b1);
        ov[j] = __floats2half2_rn(kr0, kr1);
    }
    *(uint4*)(g_Qa + qb + c0)     = *(uint4*)&oq[0];
    *(uint4*)(g_Qa + qb + c0 + 8) = *(uint4*)&oq[4];
    *(uint4*)(g_Ka + qb + c0)     = *(uint4*)&ok[0];
    *(uint4*)(g_Ka + qb + c0 + 8) = *(uint4*)&ok[4];
    *(uint4*)(g_Va + qb + c0)     = *(uint4*)&ov[0];
    *(uint4*)(g_Va + qb + c0 + 8) = *(uint4*)&ov[4];
#pragma unroll
    for (int j = 0; j < 4; j++)
        *(float4*)(g_Qt + qb + c0 + 4 * j) = *(float4*)&qt[4 * j];
}

// ============================================================================
// plain fp16 mma.sync GEMM:  C[M,Nd] = A[M,K] * B[Nd,K]^T (+bias)
// 128x128x64 CTA tile, 8 warps (2x4), 3-stage cp.async, 2 CTAs/SM.
// OUT=0: fp32 store. OUT=1: GELU fp16. OUT=2: fp16. OUT=3: fp32 + g_X residual.
// ============================================================================
#define ST_BYTES 32768          // per stage: A 16K | B 16K   (128x64 halfs each)
#define NSTAGE   3
#define GEMM_SMEM (NSTAGE * ST_BYTES)

__device__ __forceinline__ void ld_tile(uint32_t sdst,
                                        const __half* __restrict__ src,
                                        int ldk) {
    int tid = threadIdx.x;
#pragma unroll
    for (int it = 0; it < 4; it++) {
        int f   = tid + it * 256;   // 0..1023
        int row = f >> 3;           // 0..127
        int u   = f & 7;            // 16B unit within 128B row
        uint32_t d = sdst + (uint32_t)(row << 7) + (uint32_t)(((u ^ (row & 7))) << 4);
        cpa16(d, src + (size_t)row * ldk + u * 8);
    }
}

__device__ __forceinline__ void ld_stage(
    uint32_t sbase,
    const __half* __restrict__ A, const __half* __restrict__ B,
    int brow, int bcol, int K, int k0)
{
    ld_tile(sbase +     0, A + (size_t)brow * K + k0, K);
    ld_tile(sbase + 16384, B + (size_t)bcol * K + k0, K);
}

template <int OUT>
__device__ __forceinline__ void gemm_body(
    const __half* __restrict__ A, const __half* __restrict__ B,
    const float* __restrict__ bias,
    float* __restrict__ Cf, __half* __restrict__ Ch,
    int Nd, int K, int brow, int bcol, char* smem)
{
    uint32_t sb = smem_u32(smem);
    const int tid  = threadIdx.x;
    const int lane = tid & 31;
    const int wid  = tid >> 5;
    const int wr   = wid >> 2;          // 0..1 (64 m rows)
    const int wc   = wid & 3;           // 0..3 (32 n cols)

    float acc[4][4][4];
#pragma unroll
    for (int i = 0; i < 4; i++)
#pragma unroll
        for (int j = 0; j < 4; j++)
#pragma unroll
            for (int x = 0; x < 4; x++) acc[i][j][x] = 0.f;

    const int a_row = wr * 64 + (lane & 15);
    const int a_kb  = (lane & 16);
    const int b_row = wc * 32 + (lane & 7) + ((lane & 16) ? 8 : 0);
    const int b_kb  = ((lane & 8) ? 16 : 0);

    const int NCH = K >> 6;   // 64-k chunks

    ld_stage(sb, A, B, brow, bcol, K, 0);
    CP_COMMIT();
    ld_stage(sb + ST_BYTES, A, B, brow, bcol, K, 64);
    CP_COMMIT();

    int s = 0;
    for (int ch = 0; ch < NCH; ch++) {
        if (ch + 2 < NCH) {
            int sn = s + 2; if (sn >= NSTAGE) sn -= NSTAGE;
            ld_stage(sb + (uint32_t)(sn * ST_BYTES), A, B,
                     brow, bcol, K, (ch + 2) << 6);
            CP_COMMIT();
            CP_WAIT(2);
        } else if (ch + 1 < NCH) {
            CP_WAIT(1);
        } else {
            CP_WAIT(0);
        }
        __syncthreads();

        uint32_t sa = sb + (uint32_t)(s * ST_BYTES);
#pragma unroll
        for (int ks = 0; ks < 4; ks++) {
            int kso = ks * 32;
            uint32_t bmat[4][2];
#pragma unroll
            for (int jp = 0; jp < 2; jp++) {
                uint32_t addr = sa + 16384 + swoff(b_row + jp * 16, b_kb + kso);
                ldsm4(bmat[2*jp][0], bmat[2*jp][1],
                      bmat[2*jp+1][0], bmat[2*jp+1][1], addr);
            }
#pragma unroll
            for (int i = 0; i < 4; i++) {
                uint32_t a0, a1, a2, a3;
                ldsm4(a0, a1, a2, a3, sa + swoff(a_row + i * 16, a_kb + kso));
#pragma unroll
                for (int j = 0; j < 4; j++)
                    mma16816(acc[i][j], a0, a1, a2, a3, bmat[j][0], bmat[j][1]);
            }
        }
        __syncthreads();
        s++; if (s >= NSTAGE) s = 0;
    }

    const int grp = lane >> 2, qr = lane & 3;
#pragma unroll
    for (int i = 0; i < 4; i++) {
        int r0 = brow + wr * 64 + i * 16 + grp;
#pragma unroll
        for (int j = 0; j < 4; j++) {
            int col = bcol + wc * 32 + j * 8 + qr * 2;
            float b0 = bias[col], b1 = bias[col + 1];
            float v00 = acc[i][j][0] + b0, v01 = acc[i][j][1] + b1;
            float v10 = acc[i][j][2] + b0, v11 = acc[i][j][3] + b1;
            if (OUT == 0) {
                *(float2*)(Cf + (size_t)r0 * Nd + col)       = make_float2(v00, v01);
                *(float2*)(Cf + (size_t)(r0 + 8) * Nd + col) = make_float2(v10, v11);
            } else if (OUT == 1) {
                v00 = 0.5f * v00 * (1.0f + erff(v00 * 0.70710678118654752f));
                v01 = 0.5f * v01 * (1.0f + erff(v01 * 0.70710678118654752f));
                v10 = 0.5f * v10 * (1.0f + erff(v10 * 0.70710678118654752f));
                v11 = 0.5f * v11 * (1.0f + erff(v11 * 0.70710678118654752f));
                *(__half2*)(Ch + (size_t)r0 * Nd + col)       = __floats2half2_rn(v00, v01);
                *(__half2*)(Ch + (size_t)(r0 + 8) * Nd + col) = __floats2half2_rn(v10, v11);
            } else if (OUT == 2) {
                *(__half2*)(Ch + (size_t)r0 * Nd + col)       = __floats2half2_rn(v00, v01);
                *(__half2*)(Ch + (size_t)(r0 + 8) * Nd + col) = __floats2half2_rn(v10, v11);
            } else {
                // OUT == 3: add residual X, store fp32
                float2 x0 = *(const float2*)(g_X + (size_t)r0 * Nd + col);
                float2 x1 = *(const float2*)(g_X + (size_t)(r0 + 8) * Nd + col);
                *(float2*)(Cf + (size_t)r0 * Nd + col)       = make_float2(v00 + x0.x, v01 + x0.y);
                *(float2*)(Cf + (size_t)(r0 + 8) * Nd + col) = make_float2(v10 + x1.x, v11 + x1.y);
            }
        }
    }
}

template <int OUT>
__global__ __launch_bounds__(256, 2) void mma_gemm(
    const __half* __restrict__ A, const __half* __restrict__ B,
    const float* __restrict__ bias,
    float* __restrict__ Cf, __half* __restrict__ Ch,
    int Nd, int K)
{
    extern __shared__ char smem[];
    gemm_body<OUT>(A, B, bias, Cf, Ch,
                   Nd, K, blockIdx.y * 128, blockIdx.x * 128, smem);
}

// merged projection GEMM: blockIdx.z selects (Q,K,V); fp16 outputs
__global__ __launch_bounds__(256, 2) void mma_gemm_proj(
    const __half* __restrict__ A0, const __half* __restrict__ A1,
    const __half* __restrict__ A2,
    const __half* __restrict__ B0, const __half* __restrict__ B1,
    const __half* __restrict__ B2,
    const float* __restrict__ b0, const float* __restrict__ b1,
    const float* __restrict__ b2,
    __half* __restrict__ C0, __half* __restrict__ C1, __half* __restrict__ C2)
{
    extern __shared__ char smem[];
    int z = blockIdx.z;
    const __half* Aa = (z == 0) ? A0 : (z == 1) ? A1 : A2;
    const __half* Bb = (z == 0) ? B0 : (z == 1) ? B1 : B2;
    const float* bs = (z == 0) ? b0 : (z == 1) ? b1 : b2;
    __half* Cc = (z == 0) ? C0 : (z == 1) ? C1 : C2;
    gemm_body<2>(Aa, Bb, bs, nullptr, Cc,
                 CC, CC, blockIdx.y * 128, blockIdx.x * 128, smem);
}

// ============================================================================
// K4: warp-per-position windowed attention + residual + LN2.
// ============================================================================
__global__ __launch_bounds__(256) void k_attn(
    const float* __restrict__ g2, const float* __restrict__ b2)
{
    int r    = blockIdx.x * 8 + (threadIdx.x >> 5);
    int lane = threadIdx.x & 31;
    int bb = r >> 11;
    int n  = r & (NN_ - 1);
    const float scale = 0.044194173824159216f;  // 512^-0.5

    size_t qb = (size_t)r * CC;
    int cA = 8 * lane;
    int cB = 256 + 8 * lane;

    __half2 qh[8];
    *(uint4*)&qh[0] = *(const uint4*)(g_Qpa + qb + cA);
    *(uint4*)&qh[4] = *(const uint4*)(g_Qpa + qb + cB);
    float qf[16];
#pragma unroll
    for (int i = 0; i < 8; i++) {
        float2 f = __half22float2(qh[i]);
        qf[2*i] = f.x; qf[2*i+1] = f.y;
    }

    bool   valid[KH];
    size_t nb[KH];
#pragma unroll
    for (int j = 0; j < KH; j++) {
        int nn = n + j - PAD;
        valid[j] = (nn >= 0) && (nn < NN_);
        nb[j] = valid[j] ? ((size_t)(bb * NN_ + nn)) * CC : 0;
    }

    float acc[KH];
#pragma unroll
    for (int j = 0; j < KH; j++) {
        float s = 0.f;
        if (valid[j]) {
            __half2 kh[8];
            *(uint4*)&kh[0] = *(const uint4*)(g_Kpa + nb[j] + cA);
            *(uint4*)&kh[4] = *(const uint4*)(g_Kpa + nb[j] + cB);
#pragma unroll
            for (int i = 0; i < 8; i++) {
                float2 f = __half22float2(kh[i]);
                s = fmaf(qf[2*i], f.x, s);
                s = fmaf(qf[2*i+1], f.y, s);
            }
        }
        acc[j] = s;
    }
#pragma unroll
    for (int j = 0; j < KH; j++) {
#pragma unroll
        for (int o = 16; o > 0; o >>= 1)
            acc[j] += __shfl_xor_sync(0xffffffffu, acc[j], o);
    }

    float m = acc[0];
#pragma unroll
    for (int j = 1; j < KH; j++) m = fmaxf(m, acc[j]);
    float wj[KH], es = 0.f;
#pragma unroll
    for (int j = 0; j < KH; j++) { wj[j] = expf(acc[j] - m); es += wj[j]; }
    float inv = scale / es;
#pragma unroll
    for (int j = 0; j < KH; j++) wj[j] *= inv;

    float attn[16];
#pragma unroll
    for (int i = 0; i < 16; i++) attn[i] = 0.f;
#pragma unroll
    for (int j = 0; j < KH; j++) {
        if (valid[j]) {
            __half2 vh[8];
            *(uint4*)&vh[0] = *(const uint4*)(g_Vpa + nb[j] + cA);
            *(uint4*)&vh[4] = *(const uint4*)(g_Vpa + nb[j] + cB);
            float w = wj[j];
#pragma unroll
            for (int i = 0; i < 8; i++) {
                float2 f = __half22float2(vh[i]);
                attn[2*i]   = fmaf(w, f.x, attn[2*i]);
                attn[2*i+1] = fmaf(w, f.y, attn[2*i+1]);
            }
        }
    }

    float x[16];
    {
        float4 t0 = *(const float4*)(g_Qt + qb + cA);
        float4 t1 = *(const float4*)(g_Qt + qb + cA + 4);
        float4 t2 = *(const float4*)(g_Qt + qb + cB);
        float4 t3 = *(const float4*)(g_Qt + qb + cB + 4);
        x[0]=t0.x+attn[0];  x[1]=t0.y+attn[1];  x[2]=t0.z+attn[2];  x[3]=t0.w+attn[3];
        x[4]=t1.x+attn[4];  x[5]=t1.y+attn[5];  x[6]=t1.z+attn[6];  x[7]=t1.w+attn[7];
        x[8]=t2.x+attn[8];  x[9]=t2.y+attn[9];  x[10]=t2.z+attn[10]; x[11]=t2.w+attn[11];
        x[12]=t3.x+attn[12]; x[13]=t3.y+attn[13]; x[14]=t3.z+attn[14]; x[15]=t3.w+attn[15];
    }
    *(float4*)(g_X + qb + cA)     = make_float4(x[0], x[1], x[2], x[3]);
    *(float4*)(g_X + qb + cA + 4) = make_float4(x[4], x[5], x[6], x[7]);
    *(float4*)(g_X + qb + cB)     = make_float4(x[8], x[9], x[10], x[11]);
    *(float4*)(g_X + qb + cB + 4) = make_float4(x[12], x[13], x[14], x[15]);

    float xs = 0.f, xss = 0.f;
#pragma unroll
    for (int i = 0; i < 16; i++) { xs += x[i]; xss += x[i] * x[i]; }
#pragma unroll
    for (int o = 16; o > 0; o >>= 1) {
        xs  += __shfl_xor_sync(0xffffffffu, xs,  o);
        xss += __shfl_xor_sync(0xffffffffu, xss, o);
    }
    const float invC = 1.0f / CC;
    float mean = xs * invC;
    float rstd = rsqrtf(xss * invC - mean * mean + 1e-5f);

    float4 gA0 = *(const float4*)(g2 + cA);
    float4 gA1 = *(const float4*)(g2 + cA + 4);
    float4 gB0 = *(const float4*)(g2 + cB);
    float4 gB1 = *(const float4*)(g2 + cB + 4);
    float4 bA0 = *(const float4*)(b2 + cA);
    float4 bA1 = *(const float4*)(b2 + cA + 4);
    float4 bB0 = *(const float4*)(b2 + cB);
    float4 bB1 = *(const float4*)(b2 + cB + 4);
    float gg[16] = {gA0.x,gA0.y,gA0.z,gA0.w, gA1.x,gA1.y,gA1.z,gA1.w,
                    gB0.x,gB0.y,gB0.z,gB0.w, gB1.x,gB1.y,gB1.z,gB1.w};
    float bbv[16] = {bA0.x,bA0.y,bA0.z,bA0.w, bA1.x,bA1.y,bA1.z,bA1.w,
                     bB0.x,bB0.y,bB0.z,bB0.w, bB1.x,bB1.y,bB1.z,bB1.w};
    __half2 oh[8];
#pragma unroll
    for (int i = 0; i < 8; i++) {
        float v0 = (x[2*i]   - mean) * rstd * gg[2*i]   + bbv[2*i];
        float v1 = (x[2*i+1] - mean) * rstd * gg[2*i+1] + bbv[2*i+1];
        oh[i] = __floats2half2_rn(v0, v1);
    }
    *(uint4*)(g_L2a + qb + cA) = *(uint4*)&oh[0];
    *(uint4*)(g_L2a + qb + cB) = *(uint4*)&oh[4];
}

// ============================================================================
// weight prep
// ============================================================================
__global__ __launch_bounds__(256) void k_cvt(
    const float* __restrict__ src, __half* __restrict__ dst, int n)
{
    int i = blockIdx.x * 256 + threadIdx.x;
    if (i < n) dst[i] = __float2half_rn(src[i]);
}

// src [R, Cc] fp32 -> dst [Cc, R] fp16
__global__ void k_tcvt(const float* __restrict__ src,
                       __half* __restrict__ dst, int R, int Cc)
{
    __shared__ float t[32][33];
    int c0 = blockIdx.x * 32, r0 = blockIdx.y * 32;
    int tx = threadIdx.x, ty = threadIdx.y;
#pragma unroll
    for (int i = 0; i < 4; i++)
        t[ty + i * 8][tx] = src[(size_t)(r0 + ty + i * 8) * Cc + c0 + tx];
    __syncthreads();
#pragma unroll
    for (int i = 0; i < 4; i++) {
        float v = t[tx][ty + i * 8];
        dst[(size_t)(c0 + ty + i * 8) * R + r0 + tx] = __float2half_rn(v);
    }
}

// ============================================================================
// K7: out[b,c,n] = H2[r,c]   (H2 already holds X + mlp)
// ============================================================================
__global__ __launch_bounds__(256) void k_out(float* __restrict__ out)
{
    __shared__ float t[32][33];
    int bb = blockIdx.z;
    int c0 = blockIdx.y * 32;
    int n0 = blockIdx.x * 32;
    int tx = threadIdx.x;
    int ty = threadIdx.y;
#pragma unroll
    for (int i = 0; i < 4; i++) {
        int n = n0 + ty + i * 8;
        t[tx][ty + i * 8] = g_H2[((size_t)(bb * NN_ + n)) * CC + c0 + tx];
    }
    __syncthreads();
#pragma unroll
    for (int i = 0; i < 4; i++) {
        int c = c0 + ty + i * 8;
        out[(size_t)bb * CC * NN_ + (size_t)c * NN_ + n0 + tx] = t[ty + i * 8][tx];
    }
}

// ============================================================================
extern "C" void kernel_launch(void* const* d_in, const int* in_sizes, int n_in,
                              void* d_out, int out_size)
{
    const float* query = (const float*)d_in[0];
    const float* key   = (const float*)d_in[1];
    const float* qe    = (const float*)d_in[2];
    const float* ke    = (const float*)d_in[3];
    const float* wq    = (const float*)d_in[4];
    const float* bq    = (const float*)d_in[5];
    const float* wk    = (const float*)d_in[6];
    const float* bk    = (const float*)d_in[7];
    const float* wv    = (const float*)d_in[8];
    const float* bv    = (const float*)d_in[9];
    const float* gn    = (const float*)d_in[10];
    const float* bn    = (const float*)d_in[11];
    const float* g2    = (const float*)d_in[12];
    const float* b2    = (const float*)d_in[13];
    const float* w1    = (const float*)d_in[14];
    const float* b1    = (const float*)d_in[15];
    const float* w2    = (const float*)d_in[16];
    const float* b2b   = (const float*)d_in[17];
    float* out = (float*)d_out;

    float* H2;
    __half *Qa, *Ka, *Va, *Qpa, *Kpa, *Vpa, *L2a, *Ha;
    __half *wqd, *wkd, *wvd, *w1d, *w2d;
    cudaGetSymbolAddress((void**)&H2,  g_H2);
    cudaGetSymbolAddress((void**)&Qa,  g_Qa);
    cudaGetSymbolAddress((void**)&Ka,  g_Ka);
    cudaGetSymbolAddress((void**)&Va,  g_Va);
    cudaGetSymbolAddress((void**)&Qpa, g_Qpa);
    cudaGetSymbolAddress((void**)&Kpa, g_Kpa);
    cudaGetSymbolAddress((void**)&Vpa, g_Vpa);
    cudaGetSymbolAddress((void**)&L2a, g_L2a);
    cudaGetSymbolAddress((void**)&Ha,  g_Ha);
    cudaGetSymbolAddress((void**)&wqd, g_wq);
    cudaGetSymbolAddress((void**)&wkd, g_wk);
    cudaGetSymbolAddress((void**)&wvd, g_wv);
    cudaGetSymbolAddress((void**)&w1d, g_w1);
    cudaGetSymbolAddress((void**)&w2d, g_w2);

    cudaFuncSetAttribute(mma_gemm<1>,  cudaFuncAttributeMaxDynamicSharedMemorySize, GEMM_SMEM);
    cudaFuncSetAttribute(mma_gemm<3>,  cudaFuncAttributeMaxDynamicSharedMemorySize, GEMM_SMEM);
    cudaFuncSetAttribute(mma_gemm_proj, cudaFuncAttributeMaxDynamicSharedMemorySize, GEMM_SMEM);
    cudaFuncSetAttribute(k_lnfuse, cudaFuncAttributeMaxDynamicSharedMemorySize, LNF_SMEM);

    // weight prep
    k_cvt<<<(CC * CC + 255) / 256, 256>>>(wq, wqd, CC * CC);
    k_cvt<<<(CC * CC + 255) / 256, 256>>>(wk, wkd, CC * CC);
    k_cvt<<<(CC * CC + 255) / 256, 256>>>(wv, wvd, CC * CC);
    k_tcvt<<<dim3(MLPH / 32, CC / 32), dim3(32, 8)>>>(w1, w1d, CC, MLPH);
    k_tcvt<<<dim3(CC / 32, MLPH / 32), dim3(32, 8)>>>(w2, w2d, MLPH, CC);

    // 1) fused LN (single pass over inputs)
    k_lnfuse<<<dim3(NN_ / 8, BB), 256, LNF_SMEM>>>(query, key, qe, ke, gn, bn);

    // 2) projections (merged NT GEMMs, K=512) -> fp16
    {
        dim3 g(CC / 128, RR / 128, 3);
        mma_gemm_proj<<<g, 256, GEMM_SMEM>>>(
            Qa, Ka, Va, wqd, wkd, wvd,
            bq, bk, bv, Qpa, Kpa, Vpa);
    }

    // 3) attention + residual + LN2 (warp per position)
    k_attn<<<RR / 8, 256>>>(g2, b2);

    // 4) MLP1: H = gelu(L2 @ w1^T + b1)   Nd=2048, K=512
    {
        dim3 g(MLPH / 128, RR / 128);
        mma_gemm<1><<<g, 256, GEMM_SMEM>>>(L2a, w1d, b1, nullptr, Ha, MLPH, CC);
    }
    // 5) H2 = X + H @ w2^T + b2b          Nd=512, K=2048 (residual fused)
    {
        dim3 g(CC / 128, RR / 128);
        mma_gemm<3><<<g, 256, GEMM_SMEM>>>(Ha, w2d, b2b, H2, nullptr, CC, MLPH);
    }

    // 6) out = transpose(H2)
    {
        dim3 g(NN_ / 32, CC / 32, BB);
        dim3 blk(32, 8);
        k_out<<<g, blk>>>(out);
    }
}

// round 14
// speedup vs baseline: 1.8804x; 1.8804x over previous
#include <cuda_runtime.h>
#include <cuda_bf16.h>
#include <cuda_fp16.h>
#include <math.h>
#include <stdint.h>

// Problem constants (fixed shapes)
#define BB   8
#define CC   512
#define NN_  2048
#define RR   (BB * NN_)      // 16384 positions
#define MLPH 2048
#define KH   9
#define PAD  4

// ---------------- scratch (device globals; no allocs allowed) ----------------
__device__ __align__(16) float g_Qt [(size_t)RR * CC];   // raw query (residual)
__device__ __align__(16) float g_X  [(size_t)RR * CC];
__device__ __align__(16) float g_H2 [(size_t)RR * CC];   // X + mlp out (fused)
__device__ __align__(16) float4 g_stats[RR];             // qm,qrs,km,krs

// fp16 activations
__device__ __align__(16) __half g_Qa [(size_t)RR * CC];
__device__ __align__(16) __half g_Ka [(size_t)RR * CC];
__device__ __align__(16) __half g_Va [(size_t)RR * CC];
__device__ __align__(16) __half g_Qpa[(size_t)RR * CC];
__device__ __align__(16) __half g_Kpa[(size_t)RR * CC];
__device__ __align__(16) __half g_Vpa[(size_t)RR * CC];
__device__ __align__(16) __half g_L2a[(size_t)RR * CC];
__device__ __align__(16) __half g_Ha [(size_t)RR * MLPH];

// fp16 weights
__device__ __align__(16) __half g_wq[CC * CC];
__device__ __align__(16) __half g_wk[CC * CC];
__device__ __align__(16) __half g_wv[CC * CC];
__device__ __align__(16) __half g_w1[MLPH * CC];  // w1^T
__device__ __align__(16) __half g_w2[CC * MLPH];  // w2^T

// ---------------- helpers ----------------------------------------------------
__device__ __forceinline__ uint32_t smem_u32(const void* p) {
    uint32_t a;
    asm("{ .reg .u64 t; cvta.to.shared.u64 t, %1; cvt.u32.u64 %0, t; }"
        : "=r"(a) : "l"(p));
    return a;
}
__device__ __forceinline__ void cpa16(uint32_t dst, const void* src) {
    asm volatile("cp.async.cg.shared.global [%0], [%1], 16;"
                 :: "r"(dst), "l"(src) : "memory");
}
#define CP_COMMIT() asm volatile("cp.async.commit_group;" ::: "memory")
#define CP_WAIT(n)  asm volatile("cp.async.wait_group %0;" :: "n"(n) : "memory")

__device__ __forceinline__ void ldsm4(uint32_t& r0, uint32_t& r1,
                                      uint32_t& r2, uint32_t& r3, uint32_t a) {
    asm volatile("ldmatrix.sync.aligned.m8n8.x4.shared.b16 {%0,%1,%2,%3}, [%4];"
                 : "=r"(r0), "=r"(r1), "=r"(r2), "=r"(r3) : "r"(a));
}
__device__ __forceinline__ void mma16816(float* c, uint32_t a0, uint32_t a1,
                                         uint32_t a2, uint32_t a3,
                                         uint32_t b0, uint32_t b1) {
    asm volatile(
        "mma.sync.aligned.m16n8k16.row.col.f32.f16.f16.f32 "
        "{%0,%1,%2,%3}, {%4,%5,%6,%7}, {%8,%9}, {%0,%1,%2,%3};"
        : "+f"(c[0]), "+f"(c[1]), "+f"(c[2]), "+f"(c[3])
        : "r"(a0), "r"(a1), "r"(a2), "r"(a3), "r"(b0), "r"(b1));
}
// smem tile rows of 64 fp16 (128B = 8 x 16B units); unit XOR-swizzled by row&7
__device__ __forceinline__ uint32_t swoff(int row, int kb) {
    return (uint32_t)((row << 7) + ((((kb >> 4) ^ (row & 7))) << 4));
}

// ============================================================================
// K1a: per-position LN stats (coalesced along n)
// ============================================================================
__global__ __launch_bounds__(256) void k_stats(
    const float* __restrict__ q,  const float* __restrict__ k,
    const float* __restrict__ qe, const float* __restrict__ ke)
{
    int b  = blockIdx.y;
    int n0 = blockIdx.x * 32;
    int tx = threadIdx.x & 31;
    int ty = threadIdx.x >> 5;     // 0..7
    size_t base = (size_t)b * CC * NN_ + n0 + tx;

    float qs = 0.f, qss = 0.f, ks = 0.f, kss = 0.f;
    for (int c = ty; c < CC; c += 8) {
        size_t idx = base + (size_t)c * NN_;
        float qv = q[idx] + qe[idx];
        float kv = k[idx] + ke[idx];
        qs += qv; qss += qv * qv;
        ks += kv; kss += kv * kv;
    }
    __shared__ float sm[4][8][32];
    sm[0][ty][tx] = qs; sm[1][ty][tx] = qss;
    sm[2][ty][tx] = ks; sm[3][ty][tx] = kss;
    __syncthreads();
    if (ty == 0) {
        float a0 = 0.f, a1 = 0.f, a2 = 0.f, a3 = 0.f;
#pragma unroll
        for (int w = 0; w < 8; w++) {
            a0 += sm[0][w][tx]; a1 += sm[1][w][tx];
            a2 += sm[2][w][tx]; a3 += sm[3][w][tx];
        }
        const float invC = 1.0f / CC;
        float qm = a0 * invC, km = a2 * invC;
        float qrs = rsqrtf(a1 * invC - qm * qm + 1e-5f);
        float krs = rsqrtf(a3 * invC - km * km + 1e-5f);
        g_stats[b * NN_ + n0 + tx] = make_float4(qm, qrs, km, krs);
    }
}

// ============================================================================
// K1b: transpose-convert: apply LN, emit pos-major fp16 (+ raw q fp32)
// ============================================================================
__global__ __launch_bounds__(256) void k_cvtT(
    const float* __restrict__ q,  const float* __restrict__ k,
    const float* __restrict__ qe, const float* __restrict__ ke,
    const float* __restrict__ gn, const float* __restrict__ bn)
{
    __shared__ float tQE[32][33], tKE[32][33], tQ[32][33], tK[32][33];
    int b  = blockIdx.z;
    int c0 = blockIdx.y * 32;
    int n0 = blockIdx.x * 32;
    int tx = threadIdx.x;      // 0..31
    int ty = threadIdx.y;      // 0..7

#pragma unroll
    for (int i = 0; i < 4; i++) {
        int cl = ty + i * 8;
        size_t idx = (size_t)b * CC * NN_ + (size_t)(c0 + cl) * NN_ + n0 + tx;
        float qv = q[idx], kv = k[idx];
        tQ [cl][tx] = qv;
        tK [cl][tx] = kv;
        tQE[cl][tx] = qv + qe[idx];
        tKE[cl][tx] = kv + ke[idx];
    }
    __syncthreads();

    int c = c0 + tx;
    float g = gn[c], bb = bn[c];
#pragma unroll
    for (int i = 0; i < 4; i++) {
        int nl = ty + i * 8;
        int r  = b * NN_ + n0 + nl;
        float4 s = g_stats[r];
        float qo = (tQE[tx][nl] - s.x) * s.y * g + bb;
        float ko = (tKE[tx][nl] - s.z) * s.w * g + bb;
        size_t o = (size_t)r * CC + c;
        g_Qa[o] = __float2half_rn(qo);
        g_Ka[o] = __float2half_rn(ko);
        g_Va[o] = __float2half_rn(tK[tx][nl]);
        g_Qt[o] = tQ[tx][nl];
    }
}

// ============================================================================
// plain fp16 mma.sync GEMM:  C[M,Nd] = A[M,K] * B[Nd,K]^T (+bias)
// 128x128x64 CTA tile, 8 warps (2x4), 3-stage cp.async, 2 CTAs/SM.
// OUT=0: fp32 store. OUT=1: GELU fp16. OUT=2: fp16. OUT=3: fp32 + g_X residual.
// ============================================================================
#define ST_BYTES 32768          // per stage: A 16K | B 16K   (128x64 halfs each)
#define NSTAGE   3
#define GEMM_SMEM (NSTAGE * ST_BYTES)

__device__ __forceinline__ void ld_tile(uint32_t sdst,
                                        const __half* __restrict__ src,
                                        int ldk) {
    int tid = threadIdx.x;
#pragma unroll
    for (int it = 0; it < 4; it++) {
        int f   = tid + it * 256;   // 0..1023
        int row = f >> 3;           // 0..127
        int u   = f & 7;            // 16B unit within 128B row
        uint32_t d = sdst + (uint32_t)(row << 7) + (uint32_t)(((u ^ (row & 7))) << 4);
        cpa16(d, src + (size_t)row * ldk + u * 8);
    }
}

__device__ __forceinline__ void ld_stage(
    uint32_t sbase,
    const __half* __restrict__ A, const __half* __restrict__ B,
    int brow, int bcol, int K, int k0)
{
    ld_tile(sbase +     0, A + (size_t)brow * K + k0, K);
    ld_tile(sbase + 16384, B + (size_t)bcol * K + k0, K);
}

template <int OUT>
__device__ __forceinline__ void gemm_body(
    const __half* __restrict__ A, const __half* __restrict__ B,
    const float* __restrict__ bias,
    float* __restrict__ Cf, __half* __restrict__ Ch,
    int Nd, int K, int brow, int bcol, char* smem)
{
    uint32_t sb = smem_u32(smem);
    const int tid  = threadIdx.x;
    const int lane = tid & 31;
    const int wid  = tid >> 5;
    const int wr   = wid >> 2;          // 0..1 (64 m rows)
    const int wc   = wid & 3;           // 0..3 (32 n cols)

    float acc[4][4][4];
#pragma unroll
    for (int i = 0; i < 4; i++)
#pragma unroll
        for (int j = 0; j < 4; j++)
#pragma unroll
            for (int x = 0; x < 4; x++) acc[i][j][x] = 0.f;

    const int a_row = wr * 64 + (lane & 15);
    const int a_kb  = (lane & 16);
    const int b_row = wc * 32 + (lane & 7) + ((lane & 16) ? 8 : 0);
    const int b_kb  = ((lane & 8) ? 16 : 0);

    const int NCH = K >> 6;   // 64-k chunks

    ld_stage(sb, A, B, brow, bcol, K, 0);
    CP_COMMIT();
    ld_stage(sb + ST_BYTES, A, B, brow, bcol, K, 64);
    CP_COMMIT();

    int s = 0;
    for (int ch = 0; ch < NCH; ch++) {
        if (ch + 2 < NCH) {
            int sn = s + 2; if (sn >= NSTAGE) sn -= NSTAGE;
            ld_stage(sb + (uint32_t)(sn * ST_BYTES), A, B,
                     brow, bcol, K, (ch + 2) << 6);
            CP_COMMIT();
            CP_WAIT(2);
        } else if (ch + 1 < NCH) {
            CP_WAIT(1);
        } else {
            CP_WAIT(0);
        }
        __syncthreads();

        uint32_t sa = sb + (uint32_t)(s * ST_BYTES);
#pragma unroll
        for (int ks = 0; ks < 4; ks++) {
            int kso = ks * 32;
            uint32_t bmat[4][2];
#pragma unroll
            for (int jp = 0; jp < 2; jp++) {
                uint32_t addr = sa + 16384 + swoff(b_row + jp * 16, b_kb + kso);
                ldsm4(bmat[2*jp][0], bmat[2*jp][1],
                      bmat[2*jp+1][0], bmat[2*jp+1][1], addr);
            }
#pragma unroll
            for (int i = 0; i < 4; i++) {
                uint32_t a0, a1, a2, a3;
                ldsm4(a0, a1, a2, a3, sa + swoff(a_row + i * 16, a_kb + kso));
#pragma unroll
                for (int j = 0; j < 4; j++)
                    mma16816(acc[i][j], a0, a1, a2, a3, bmat[j][0], bmat[j][1]);
            }
        }
        __syncthreads();
        s++; if (s >= NSTAGE) s = 0;
    }

    const int grp = lane >> 2, qr = lane & 3;
#pragma unroll
    for (int i = 0; i < 4; i++) {
        int r0 = brow + wr * 64 + i * 16 + grp;
#pragma unroll
        for (int j = 0; j < 4; j++) {
            int col = bcol + wc * 32 + j * 8 + qr * 2;
            float b0 = bias[col], b1 = bias[col + 1];
            float v00 = acc[i][j][0] + b0, v01 = acc[i][j][1] + b1;
            float v10 = acc[i][j][2] + b0, v11 = acc[i][j][3] + b1;
            if (OUT == 0) {
                *(float2*)(Cf + (size_t)r0 * Nd + col)       = make_float2(v00, v01);
                *(float2*)(Cf + (size_t)(r0 + 8) * Nd + col) = make_float2(v10, v11);
            } else if (OUT == 1) {
                v00 = 0.5f * v00 * (1.0f + erff(v00 * 0.70710678118654752f));
                v01 = 0.5f * v01 * (1.0f + erff(v01 * 0.70710678118654752f));
                v10 = 0.5f * v10 * (1.0f + erff(v10 * 0.70710678118654752f));
                v11 = 0.5f * v11 * (1.0f + erff(v11 * 0.70710678118654752f));
                *(__half2*)(Ch + (size_t)r0 * Nd + col)       = __floats2half2_rn(v00, v01);
                *(__half2*)(Ch + (size_t)(r0 + 8) * Nd + col) = __floats2half2_rn(v10, v11);
            } else if (OUT == 2) {
                *(__half2*)(Ch + (size_t)r0 * Nd + col)       = __floats2half2_rn(v00, v01);
                *(__half2*)(Ch + (size_t)(r0 + 8) * Nd + col) = __floats2half2_rn(v10, v11);
            } else {
                // OUT == 3: add residual X, store fp32
                float2 x0 = *(const float2*)(g_X + (size_t)r0 * Nd + col);
                float2 x1 = *(const float2*)(g_X + (size_t)(r0 + 8) * Nd + col);
                *(float2*)(Cf + (size_t)r0 * Nd + col)       = make_float2(v00 + x0.x, v01 + x0.y);
                *(float2*)(Cf + (size_t)(r0 + 8) * Nd + col) = make_float2(v10 + x1.x, v11 + x1.y);
            }
        }
    }
}

template <int OUT>
__global__ __launch_bounds__(256, 2) void mma_gemm(
    const __half* __restrict__ A, const __half* __restrict__ B,
    const float* __restrict__ bias,
    float* __restrict__ Cf, __half* __restrict__ Ch,
    int Nd, int K)
{
    extern __shared__ char smem[];
    gemm_body<OUT>(A, B, bias, Cf, Ch,
                   Nd, K, blockIdx.y * 128, blockIdx.x * 128, smem);
}

// merged projection GEMM: blockIdx.z selects (Q,K,V); fp16 outputs
__global__ __launch_bounds__(256, 2) void mma_gemm_proj(
    const __half* __restrict__ A0, const __half* __restrict__ A1,
    const __half* __restrict__ A2,
    const __half* __restrict__ B0, const __half* __restrict__ B1,
    const __half* __restrict__ B2,
    const float* __restrict__ b0, const float* __restrict__ b1,
    const float* __restrict__ b2,
    __half* __restrict__ C0, __half* __restrict__ C1, __half* __restrict__ C2)
{
    extern __shared__ char smem[];
    int z = blockIdx.z;
    const __half* Aa = (z == 0) ? A0 : (z == 1) ? A1 : A2;
    const __half* Bb = (z == 0) ? B0 : (z == 1) ? B1 : B2;
    const float* bs = (z == 0) ? b0 : (z == 1) ? b1 : b2;
    __half* Cc = (z == 0) ? C0 : (z == 1) ? C1 : C2;
    gemm_body<2>(Aa, Bb, bs, nullptr, Cc,
                 CC, CC, blockIdx.y * 128, blockIdx.x * 128, smem);
}

// ============================================================================
// K4: warp-per-position windowed attention + residual + LN2.
// No smem, no __syncthreads; warp-butterfly reductions.
// ============================================================================
__global__ __launch_bounds__(256) void k_attn(
    const float* __restrict__ g2, const float* __restrict__ b2)
{
    int r    = blockIdx.x * 8 + (threadIdx.x >> 5);
    int lane = threadIdx.x & 31;
    int bb = r >> 11;
    int n  = r & (NN_ - 1);
    const float scale = 0.044194173824159216f;  // 512^-0.5

    size_t qb = (size_t)r * CC;
    int cA = 8 * lane;
    int cB = 256 + 8 * lane;

    __half2 qh[8];
    *(uint4*)&qh[0] = *(const uint4*)(g_Qpa + qb + cA);
    *(uint4*)&qh[4] = *(const uint4*)(g_Qpa + qb + cB);
    float qf[16];
#pragma unroll
    for (int i = 0; i < 8; i++) {
        float2 f = __half22float2(qh[i]);
        qf[2*i] = f.x; qf[2*i+1] = f.y;
    }

    bool   valid[KH];
    size_t nb[KH];
#pragma unroll
    for (int j = 0; j < KH; j++) {
        int nn = n + j - PAD;
        valid[j] = (nn >= 0) && (nn < NN_);
        nb[j] = valid[j] ? ((size_t)(bb * NN_ + nn)) * CC : 0;
    }

    float acc[KH];
#pragma unroll
    for (int j = 0; j < KH; j++) {
        float s = 0.f;
        if (valid[j]) {
            __half2 kh[8];
            *(uint4*)&kh[0] = *(const uint4*)(g_Kpa + nb[j] + cA);
            *(uint4*)&kh[4] = *(const uint4*)(g_Kpa + nb[j] + cB);
#pragma unroll
            for (int i = 0; i < 8; i++) {
                float2 f = __half22float2(kh[i]);
                s = fmaf(qf[2*i], f.x, s);
                s = fmaf(qf[2*i+1], f.y, s);
            }
        }
        acc[j] = s;
    }
#pragma unroll
    for (int j = 0; j < KH; j++) {
#pragma unroll
        for (int o = 16; o > 0; o >>= 1)
            acc[j] += __shfl_xor_sync(0xffffffffu, acc[j], o);
    }

    float m = acc[0];
#pragma unroll
    for (int j = 1; j < KH; j++) m = fmaxf(m, acc[j]);
    float wj[KH], es = 0.f;
#pragma unroll
    for (int j = 0; j < KH; j++) { wj[j] = expf(acc[j] - m); es += wj[j]; }
    float inv = scale / es;
#pragma unroll
    for (int j = 0; j < KH; j++) wj[j] *= inv;

    float attn[16];
#pragma unroll
    for (int i = 0; i < 16; i++) attn[i] = 0.f;
#pragma unroll
    for (int j = 0; j < KH; j++) {
        if (valid[j]) {
            __half2 vh[8];
            *(uint4*)&vh[0] = *(const uint4*)(g_Vpa + nb[j] + cA);
            *(uint4*)&vh[4] = *(const uint4*)(g_Vpa + nb[j] + cB);
            float w = wj[j];
#pragma unroll
            for (int i = 0; i < 8; i++) {
                float2 f = __half22float2(vh[i]);
                attn[2*i]   = fmaf(w, f.x, attn[2*i]);
                attn[2*i+1] = fmaf(w, f.y, attn[2*i+1]);
            }
        }
    }

    float x[16];
    {
        float4 t0 = *(const float4*)(g_Qt + qb + cA);
        float4 t1 = *(const float4*)(g_Qt + qb + cA + 4);
        float4 t2 = *(const float4*)(g_Qt + qb + cB);
        float4 t3 = *(const float4*)(g_Qt + qb + cB + 4);
        x[0]=t0.x+attn[0];  x[1]=t0.y+attn[1];  x[2]=t0.z+attn[2];  x[3]=t0.w+attn[3];
        x[4]=t1.x+attn[4];  x[5]=t1.y+attn[5];  x[6]=t1.z+attn[6];  x[7]=t1.w+attn[7];
        x[8]=t2.x+attn[8];  x[9]=t2.y+attn[9];  x[10]=t2.z+attn[10]; x[11]=t2.w+attn[11];
        x[12]=t3.x+attn[12]; x[13]=t3.y+attn[13]; x[14]=t3.z+attn[14]; x[15]=t3.w+attn[15];
    }
    *(float4*)(g_X + qb + cA)     = make_float4(x[0], x[1], x[2], x[3]);
    *(float4*)(g_X + qb + cA + 4) = make_float4(x[4], x[5], x[6], x[7]);
    *(float4*)(g_X + qb + cB)     = make_float4(x[8], x[9], x[10], x[11]);
    *(float4*)(g_X + qb + cB + 4) = make_float4(x[12], x[13], x[14], x[15]);

    float xs = 0.f, xss = 0.f;
#pragma unroll
    for (int i = 0; i < 16; i++) { xs += x[i]; xss += x[i] * x[i]; }
#pragma unroll
    for (int o = 16; o > 0; o >>= 1) {
        xs  += __shfl_xor_sync(0xffffffffu, xs,  o);
        xss += __shfl_xor_sync(0xffffffffu, xss, o);
    }
    const float invC = 1.0f / CC;
    float mean = xs * invC;
    float rstd = rsqrtf(xss * invC - mean * mean + 1e-5f);

    float4 gA0 = *(const float4*)(g2 + cA);
    float4 gA1 = *(const float4*)(g2 + cA + 4);
    float4 gB0 = *(const float4*)(g2 + cB);
    float4 gB1 = *(const float4*)(g2 + cB + 4);
    float4 bA0 = *(const float4*)(b2 + cA);
    float4 bA1 = *(const float4*)(b2 + cA + 4);
    float4 bB0 = *(const float4*)(b2 + cB);
    float4 bB1 = *(const float4*)(b2 + cB + 4);
    float gg[16] = {gA0.x,gA0.y,gA0.z,gA0.w, gA1.x,gA1.y,gA1.z,gA1.w,
                    gB0.x,gB0.y,gB0.z,gB0.w, gB1.x,gB1.y,gB1.z,gB1.w};
    float bbv[16] = {bA0.x,bA0.y,bA0.z,bA0.w, bA1.x,bA1.y,bA1.z,bA1.w,
                     bB0.x,bB0.y,bB0.z,bB0.w, bB1.x,bB1.y,bB1.z,bB1.w};
    __half2 oh[8];
#pragma unroll
    for (int i = 0; i < 8; i++) {
        float v0 = (x[2*i]   - mean) * rstd * gg[2*i]   + bbv[2*i];
        float v1 = (x[2*i+1] - mean) * rstd * gg[2*i+1] + bbv[2*i+1];
        oh[i] = __floats2half2_rn(v0, v1);
    }
    *(uint4*)(g_L2a + qb + cA) = *(uint4*)&oh[0];
    *(uint4*)(g_L2a + qb + cB) = *(uint4*)&oh[4];
}

// ============================================================================
// weight prep
// ============================================================================
__global__ __launch_bounds__(256) void k_cvt(
    const float* __restrict__ src, __half* __restrict__ dst, int n)
{
    int i = blockIdx.x * 256 + threadIdx.x;
    if (i < n) dst[i] = __float2half_rn(src[i]);
}

// src [R, Cc] fp32 -> dst [Cc, R] fp16
__global__ void k_tcvt(const float* __restrict__ src,
                       __half* __restrict__ dst, int R, int Cc)
{
    __shared__ float t[32][33];
    int c0 = blockIdx.x * 32, r0 = blockIdx.y * 32;
    int tx = threadIdx.x, ty = threadIdx.y;
#pragma unroll
    for (int i = 0; i < 4; i++)
        t[ty + i * 8][tx] = src[(size_t)(r0 + ty + i * 8) * Cc + c0 + tx];
    __syncthreads();
#pragma unroll
    for (int i = 0; i < 4; i++) {
        float v = t[tx][ty + i * 8];
        dst[(size_t)(c0 + ty + i * 8) * R + r0 + tx] = __float2half_rn(v);
    }
}

// ============================================================================
// K7: out[b,c,n] = H2[r,c]   (H2 already holds X + mlp)
// ============================================================================
__global__ __launch_bounds__(256) void k_out(float* __restrict__ out)
{
    __shared__ float t[32][33];
    int bb = blockIdx.z;
    int c0 = blockIdx.y * 32;
    int n0 = blockIdx.x * 32;
    int tx = threadIdx.x;
    int ty = threadIdx.y;
#pragma unroll
    for (int i = 0; i < 4; i++) {
        int n = n0 + ty + i * 8;
        t[tx][ty + i * 8] = g_H2[((size_t)(bb * NN_ + n)) * CC + c0 + tx];
    }
    __syncthreads();
#pragma unroll
    for (int i = 0; i < 4; i++) {
        int c = c0 + ty + i * 8;
        out[(size_t)bb * CC * NN_ + (size_t)c * NN_ + n0 + tx] = t[ty + i * 8][tx];
    }
}

// ============================================================================
extern "C" void kernel_launch(void* const* d_in, const int* in_sizes, int n_in,
                              void* d_out, int out_size)
{
    const float* query = (const float*)d_in[0];
    const float* key   = (const float*)d_in[1];
    const float* qe    = (const float*)d_in[2];
    const float* ke    = (const float*)d_in[3];
    const float* wq    = (const float*)d_in[4];
    const float* bq    = (const float*)d_in[5];
    const float* wk    = (const float*)d_in[6];
    const float* bk    = (const float*)d_in[7];
    const float* wv    = (const float*)d_in[8];
    const float* bv    = (const float*)d_in[9];
    const float* gn    = (const float*)d_in[10];
    const float* bn    = (const float*)d_in[11];
    const float* g2    = (const float*)d_in[12];
    const float* b2    = (const float*)d_in[13];
    const float* w1    = (const float*)d_in[14];
    const float* b1    = (const float*)d_in[15];
    const float* w2    = (const float*)d_in[16];
    const float* b2b   = (const float*)d_in[17];
    float* out = (float*)d_out;

    float* H2;
    __half *Qa, *Ka, *Va, *Qpa, *Kpa, *Vpa, *L2a, *Ha;
    __half *wqd, *wkd, *wvd, *w1d, *w2d;
    cudaGetSymbolAddress((void**)&H2,  g_H2);
    cudaGetSymbolAddress((void**)&Qa,  g_Qa);
    cudaGetSymbolAddress((void**)&Ka,  g_Ka);
    cudaGetSymbolAddress((void**)&Va,  g_Va);
    cudaGetSymbolAddress((void**)&Qpa, g_Qpa);
    cudaGetSymbolAddress((void**)&Kpa, g_Kpa);
    cudaGetSymbolAddress((void**)&Vpa, g_Vpa);
    cudaGetSymbolAddress((void**)&L2a, g_L2a);
    cudaGetSymbolAddress((void**)&Ha,  g_Ha);
    cudaGetSymbolAddress((void**)&wqd, g_wq);
    cudaGetSymbolAddress((void**)&wkd, g_wk);
    cudaGetSymbolAddress((void**)&wvd, g_wv);
    cudaGetSymbolAddress((void**)&w1d, g_w1);
    cudaGetSymbolAddress((void**)&w2d, g_w2);

    cudaFuncSetAttribute(mma_gemm<1>,  cudaFuncAttributeMaxDynamicSharedMemorySize, GEMM_SMEM);
    cudaFuncSetAttribute(mma_gemm<3>,  cudaFuncAttributeMaxDynamicSharedMemorySize, GEMM_SMEM);
    cudaFuncSetAttribute(mma_gemm_proj, cudaFuncAttributeMaxDynamicSharedMemorySize, GEMM_SMEM);

    // weight prep
    k_cvt<<<(CC * CC + 255) / 256, 256>>>(wq, wqd, CC * CC);
    k_cvt<<<(CC * CC + 255) / 256, 256>>>(wk, wkd, CC * CC);
    k_cvt<<<(CC * CC + 255) / 256, 256>>>(wv, wvd, CC * CC);
    k_tcvt<<<dim3(MLPH / 32, CC / 32), dim3(32, 8)>>>(w1, w1d, CC, MLPH);
    k_tcvt<<<dim3(CC / 32, MLPH / 32), dim3(32, 8)>>>(w2, w2d, MLPH, CC);

    // 1) LN stats + transpose-convert (R12 proven-coalesced path)
    k_stats<<<dim3(NN_ / 32, BB), 256>>>(query, key, qe, ke);
    k_cvtT<<<dim3(NN_ / 32, CC / 32, BB), dim3(32, 8)>>>(query, key, qe, ke, gn, bn);

    // 2) projections (merged NT GEMMs, K=512) -> fp16
    {
        dim3 g(CC / 128, RR / 128, 3);
        mma_gemm_proj<<<g, 256, GEMM_SMEM>>>(
            Qa, Ka, Va, wqd, wkd, wvd,
            bq, bk, bv, Qpa, Kpa, Vpa);
    }

    // 3) attention + residual + LN2 (warp per position)
    k_attn<<<RR / 8, 256>>>(g2, b2);

    // 4) MLP1: H = gelu(L2 @ w1^T + b1)   Nd=2048, K=512
    {
        dim3 g(MLPH / 128, RR / 128);
        mma_gemm<1><<<g, 256, GEMM_SMEM>>>(L2a, w1d, b1, nullptr, Ha, MLPH, CC);
    }
    // 5) H2 = X + H @ w2^T + b2b          Nd=512, K=2048 (residual fused)
    {
        dim3 g(CC / 128, RR / 128);
        mma_gemm<3><<<g, 256, GEMM_SMEM>>>(Ha, w2d, b2b, H2, nullptr, CC, MLPH);
    }

    // 6) out = transpose(H2)
    {
        dim3 g(NN_ / 32, CC / 32, BB);
        dim3 blk(32, 8);
        k_out<<<g, blk>>>(out);
    }
}

// round 16
// speedup vs baseline: 1.9484x; 1.0362x over previous
#include <cuda_runtime.h>
#include <cuda_bf16.h>
#include <cuda_fp16.h>
#include <math.h>
#include <stdint.h>

// Problem constants (fixed shapes)
#define BB   8
#define CC   512
#define NN_  2048
#define RR   (BB * NN_)      // 16384 positions
#define MLPH 2048
#define KH   9
#define PAD  4

// ---------------- scratch (device globals; no allocs allowed) ----------------
__device__ __align__(16) float4 g_stats[RR];             // qm,qrs,km,krs

// fp16 activations
__device__ __align__(16) __half g_Qth[(size_t)RR * CC];   // raw query (residual)
__device__ __align__(16) __half g_Xh [(size_t)RR * CC];   // query + attn
__device__ __align__(16) __half g_Qa [(size_t)RR * CC];
__device__ __align__(16) __half g_Ka [(size_t)RR * CC];
__device__ __align__(16) __half g_Va [(size_t)RR * CC];
__device__ __align__(16) __half g_Qpa[(size_t)RR * CC];
__device__ __align__(16) __half g_Kpa[(size_t)RR * CC];
__device__ __align__(16) __half g_Vpa[(size_t)RR * CC];
__device__ __align__(16) __half g_L2a[(size_t)RR * CC];
__device__ __align__(16) __half g_Ha [(size_t)RR * MLPH];

// fp16 weights
__device__ __align__(16) __half g_wq[CC * CC];
__device__ __align__(16) __half g_wk[CC * CC];
__device__ __align__(16) __half g_wv[CC * CC];
__device__ __align__(16) __half g_w1[MLPH * CC];  // w1^T
__device__ __align__(16) __half g_w2[CC * MLPH];  // w2^T

// ---------------- helpers ----------------------------------------------------
__device__ __forceinline__ uint32_t smem_u32(const void* p) {
    uint32_t a;
    asm("{ .reg .u64 t; cvta.to.shared.u64 t, %1; cvt.u32.u64 %0, t; }"
        : "=r"(a) : "l"(p));
    return a;
}
__device__ __forceinline__ void cpa16(uint32_t dst, const void* src) {
    asm volatile("cp.async.cg.shared.global [%0], [%1], 16;"
                 :: "r"(dst), "l"(src) : "memory");
}
#define CP_COMMIT() asm volatile("cp.async.commit_group;" ::: "memory")
#define CP_WAIT(n)  asm volatile("cp.async.wait_group %0;" :: "n"(n) : "memory")

__device__ __forceinline__ void ldsm4(uint32_t& r0, uint32_t& r1,
                                      uint32_t& r2, uint32_t& r3, uint32_t a) {
    asm volatile("ldmatrix.sync.aligned.m8n8.x4.shared.b16 {%0,%1,%2,%3}, [%4];"
                 : "=r"(r0), "=r"(r1), "=r"(r2), "=r"(r3) : "r"(a));
}
__device__ __forceinline__ void mma16816(float* c, uint32_t a0, uint32_t a1,
                                         uint32_t a2, uint32_t a3,
                                         uint32_t b0, uint32_t b1) {
    asm volatile(
        "mma.sync.aligned.m16n8k16.row.col.f32.f16.f16.f32 "
        "{%0,%1,%2,%3}, {%4,%5,%6,%7}, {%8,%9}, {%0,%1,%2,%3};"
        : "+f"(c[0]), "+f"(c[1]), "+f"(c[2]), "+f"(c[3])
        : "r"(a0), "r"(a1), "r"(a2), "r"(a3), "r"(b0), "r"(b1));
}
// smem tile rows of 64 fp16 (128B = 8 x 16B units); unit XOR-swizzled by row&7
__device__ __forceinline__ uint32_t swoff(int row, int kb) {
    return (uint32_t)((row << 7) + ((((kb >> 4) ^ (row & 7))) << 4));
}

// ============================================================================
// K1a: per-position LN stats (coalesced along n)
// ============================================================================
__global__ __launch_bounds__(256) void k_stats(
    const float* __restrict__ q,  const float* __restrict__ k,
    const float* __restrict__ qe, const float* __restrict__ ke)
{
    int b  = blockIdx.y;
    int n0 = blockIdx.x * 32;
    int tx = threadIdx.x & 31;
    int ty = threadIdx.x >> 5;     // 0..7
    size_t base = (size_t)b * CC * NN_ + n0 + tx;

    float qs = 0.f, qss = 0.f, ks = 0.f, kss = 0.f;
    for (int c = ty; c < CC; c += 8) {
        size_t idx = base + (size_t)c * NN_;
        float qv = q[idx] + qe[idx];
        float kv = k[idx] + ke[idx];
        qs += qv; qss += qv * qv;
        ks += kv; kss += kv * kv;
    }
    __shared__ float sm[4][8][32];
    sm[0][ty][tx] = qs; sm[1][ty][tx] = qss;
    sm[2][ty][tx] = ks; sm[3][ty][tx] = kss;
    __syncthreads();
    if (ty == 0) {
        float a0 = 0.f, a1 = 0.f, a2 = 0.f, a3 = 0.f;
#pragma unroll
        for (int w = 0; w < 8; w++) {
            a0 += sm[0][w][tx]; a1 += sm[1][w][tx];
            a2 += sm[2][w][tx]; a3 += sm[3][w][tx];
        }
        const float invC = 1.0f / CC;
        float qm = a0 * invC, km = a2 * invC;
        float qrs = rsqrtf(a1 * invC - qm * qm + 1e-5f);
        float krs = rsqrtf(a3 * invC - km * km + 1e-5f);
        g_stats[b * NN_ + n0 + tx] = make_float4(qm, qrs, km, krs);
    }
}

// ============================================================================
// K1b: transpose-convert: apply LN, emit pos-major fp16 (+ raw q fp16)
// ============================================================================
__global__ __launch_bounds__(256) void k_cvtT(
    const float* __restrict__ q,  const float* __restrict__ k,
    const float* __restrict__ qe, const float* __restrict__ ke,
    const float* __restrict__ gn, const float* __restrict__ bn)
{
    __shared__ float tQE[32][33], tKE[32][33], tQ[32][33], tK[32][33];
    int b  = blockIdx.z;
    int c0 = blockIdx.y * 32;
    int n0 = blockIdx.x * 32;
    int tx = threadIdx.x;      // 0..31
    int ty = threadIdx.y;      // 0..7

#pragma unroll
    for (int i = 0; i < 4; i++) {
        int cl = ty + i * 8;
        size_t idx = (size_t)b * CC * NN_ + (size_t)(c0 + cl) * NN_ + n0 + tx;
        float qv = q[idx], kv = k[idx];
        tQ [cl][tx] = qv;
        tK [cl][tx] = kv;
        tQE[cl][tx] = qv + qe[idx];
        tKE[cl][tx] = kv + ke[idx];
    }
    __syncthreads();

    int c = c0 + tx;
    float g = gn[c], bb = bn[c];
#pragma unroll
    for (int i = 0; i < 4; i++) {
        int nl = ty + i * 8;
        int r  = b * NN_ + n0 + nl;
        float4 s = g_stats[r];
        float qo = (tQE[tx][nl] - s.x) * s.y * g + bb;
        float ko = (tKE[tx][nl] - s.z) * s.w * g + bb;
        size_t o = (size_t)r * CC + c;
        g_Qa[o]  = __float2half_rn(qo);
        g_Ka[o]  = __float2half_rn(ko);
        g_Va[o]  = __float2half_rn(tK[tx][nl]);
        g_Qth[o] = __float2half_rn(tQ[tx][nl]);
    }
}

// ============================================================================
// plain fp16 mma.sync GEMM:  C[M,Nd] = A[M,K] * B[Nd,K]^T (+bias)
// 128x128x64 CTA tile, 8 warps (2x4), 3-stage cp.async, 2 CTAs/SM.
// OUT=1: GELU fp16. OUT=2: fp16.
// OUT=3: + g_Xh residual, transpose in smem, store channel-major fp32 output.
// ============================================================================
#define ST_BYTES 32768          // per stage: A 16K | B 16K   (128x64 halfs each)
#define NSTAGE   3
#define GEMM_SMEM (NSTAGE * ST_BYTES)

__device__ __forceinline__ void ld_tile(uint32_t sdst,
                                        const __half* __restrict__ src,
                                        int ldk) {
    int tid = threadIdx.x;
#pragma unroll
    for (int it = 0; it < 4; it++) {
        int f   = tid + it * 256;   // 0..1023
        int row = f >> 3;           // 0..127
        int u   = f & 7;            // 16B unit within 128B row
        uint32_t d = sdst + (uint32_t)(row << 7) + (uint32_t)(((u ^ (row & 7))) << 4);
        cpa16(d, src + (size_t)row * ldk + u * 8);
    }
}

__device__ __forceinline__ void ld_stage(
    uint32_t sbase,
    const __half* __restrict__ A, const __half* __restrict__ B,
    int brow, int bcol, int K, int k0)
{
    ld_tile(sbase +     0, A + (size_t)brow * K + k0, K);
    ld_tile(sbase + 16384, B + (size_t)bcol * K + k0, K);
}

template <int OUT>
__device__ __forceinline__ void gemm_body(
    const __half* __restrict__ A, const __half* __restrict__ B,
    const float* __restrict__ bias,
    float* __restrict__ Cf, __half* __restrict__ Ch,
    int Nd, int K, int brow, int bcol, char* smem)
{
    uint32_t sb = smem_u32(smem);
    const int tid  = threadIdx.x;
    const int lane = tid & 31;
    const int wid  = tid >> 5;
    const int wr   = wid >> 2;          // 0..1 (64 m rows)
    const int wc   = wid & 3;           // 0..3 (32 n cols)

    float acc[4][4][4];
#pragma unroll
    for (int i = 0; i < 4; i++)
#pragma unroll
        for (int j = 0; j < 4; j++)
#pragma unroll
            for (int x = 0; x < 4; x++) acc[i][j][x] = 0.f;

    const int a_row = wr * 64 + (lane & 15);
    const int a_kb  = (lane & 16);
    const int b_row = wc * 32 + (lane & 7) + ((lane & 16) ? 8 : 0);
    const int b_kb  = ((lane & 8) ? 16 : 0);

    const int NCH = K >> 6;   // 64-k chunks

    ld_stage(sb, A, B, brow, bcol, K, 0);
    CP_COMMIT();
    ld_stage(sb + ST_BYTES, A, B, brow, bcol, K, 64);
    CP_COMMIT();

    int s = 0;
    for (int ch = 0; ch < NCH; ch++) {
        if (ch + 2 < NCH) {
            int sn = s + 2; if (sn >= NSTAGE) sn -= NSTAGE;
            ld_stage(sb + (uint32_t)(sn * ST_BYTES), A, B,
                     brow, bcol, K, (ch + 2) << 6);
            CP_COMMIT();
            CP_WAIT(2);
        } else if (ch + 1 < NCH) {
            CP_WAIT(1);
        } else {
            CP_WAIT(0);
        }
        __syncthreads();

        uint32_t sa = sb + (uint32_t)(s * ST_BYTES);
#pragma unroll
        for (int ks = 0; ks < 4; ks++) {
            int kso = ks * 32;
            uint32_t bmat[4][2];
#pragma unroll
            for (int jp = 0; jp < 2; jp++) {
                uint32_t addr = sa + 16384 + swoff(b_row + jp * 16, b_kb + kso);
                ldsm4(bmat[2*jp][0], bmat[2*jp][1],
                      bmat[2*jp+1][0], bmat[2*jp+1][1], addr);
            }
#pragma unroll
            for (int i = 0; i < 4; i++) {
                uint32_t a0, a1, a2, a3;
                ldsm4(a0, a1, a2, a3, sa + swoff(a_row + i * 16, a_kb + kso));
#pragma unroll
                for (int j = 0; j < 4; j++)
                    mma16816(acc[i][j], a0, a1, a2, a3, bmat[j][0], bmat[j][1]);
            }
        }
        __syncthreads();
        s++; if (s >= NSTAGE) s = 0;
    }

    const int grp = lane >> 2, qr = lane & 3;

    if (OUT == 3) {
        // residual + transpose staging (smem free after last mainloop barrier)
        float* stf = (float*)smem;      // [128 cols][pitch 129 rows]
#pragma unroll
        for (int i = 0; i < 4; i++) {
            int lr = wr * 64 + i * 16 + grp;        // local row
            int r0 = brow + lr;
#pragma unroll
            for (int j = 0; j < 4; j++) {
                int lc = wc * 32 + j * 8 + qr * 2;  // local col
                int col = bcol + lc;
                float b0 = bias[col], b1 = bias[col + 1];
                __half2 x0 = *(const __half2*)(g_Xh + (size_t)r0 * Nd + col);
                __half2 x1 = *(const __half2*)(g_Xh + (size_t)(r0 + 8) * Nd + col);
                float2 xf0 = __half22float2(x0);
                float2 xf1 = __half22float2(x1);
                stf[lc * 129 + lr]           = acc[i][j][0] + b0 + xf0.x;
                stf[(lc + 1) * 129 + lr]     = acc[i][j][1] + b1 + xf0.y;
                stf[lc * 129 + lr + 8]       = acc[i][j][2] + b0 + xf1.x;
                stf[(lc + 1) * 129 + lr + 8] = acc[i][j][3] + b1 + xf1.y;
            }
        }
        __syncthreads();
        // coalesced channel-major write: out[(b*CC + c) * NN_ + n]
        int bb2 = brow >> 11;
        int n0  = brow & (NN_ - 1);
        size_t obase = ((size_t)bb2 * CC + bcol) * NN_ + n0;
        for (int c = wid; c < 128; c += 8) {
            const float* src = stf + c * 129;
            float* dst = Cf + obase + (size_t)c * NN_;
            dst[lane]      = src[lane];
            dst[lane + 32] = src[lane + 32];
            dst[lane + 64] = src[lane + 64];
            dst[lane + 96] = src[lane + 96];
        }
        return;
    }

#pragma unroll
    for (int i = 0; i < 4; i++) {
        int r0 = brow + wr * 64 + i * 16 + grp;
#pragma unroll
        for (int j = 0; j < 4; j++) {
            int col = bcol + wc * 32 + j * 8 + qr * 2;
            float b0 = bias[col], b1 = bias[col + 1];
            float v00 = acc[i][j][0] + b0, v01 = acc[i][j][1] + b1;
            float v10 = acc[i][j][2] + b0, v11 = acc[i][j][3] + b1;
            if (OUT == 1) {
                v00 = 0.5f * v00 * (1.0f + erff(v00 * 0.70710678118654752f));
                v01 = 0.5f * v01 * (1.0f + erff(v01 * 0.70710678118654752f));
                v10 = 0.5f * v10 * (1.0f + erff(v10 * 0.70710678118654752f));
                v11 = 0.5f * v11 * (1.0f + erff(v11 * 0.70710678118654752f));
            }
            *(__half2*)(Ch + (size_t)r0 * Nd + col)       = __floats2half2_rn(v00, v01);
            *(__half2*)(Ch + (size_t)(r0 + 8) * Nd + col) = __floats2half2_rn(v10, v11);
        }
    }
}

template <int OUT>
__global__ __launch_bounds__(256, 2) void mma_gemm(
    const __half* __restrict__ A, const __half* __restrict__ B,
    const float* __restrict__ bias,
    float* __restrict__ Cf, __half* __restrict__ Ch,
    int Nd, int K)
{
    extern __shared__ char smem[];
    gemm_body<OUT>(A, B, bias, Cf, Ch,
                   Nd, K, blockIdx.y * 128, blockIdx.x * 128, smem);
}

// merged projection GEMM: blockIdx.z selects (Q,K,V); fp16 outputs
__global__ __launch_bounds__(256, 2) void mma_gemm_proj(
    const __half* __restrict__ A0, const __half* __restrict__ A1,
    const __half* __restrict__ A2,
    const __half* __restrict__ B0, const __half* __restrict__ B1,
    const __half* __restrict__ B2,
    const float* __restrict__ b0, const float* __restrict__ b1,
    const float* __restrict__ b2,
    __half* __restrict__ C0, __half* __restrict__ C1, __half* __restrict__ C2)
{
    extern __shared__ char smem[];
    int z = blockIdx.z;
    const __half* Aa = (z == 0) ? A0 : (z == 1) ? A1 : A2;
    const __half* Bb = (z == 0) ? B0 : (z == 1) ? B1 : B2;
    const float* bs = (z == 0) ? b0 : (z == 1) ? b1 : b2;
    __half* Cc = (z == 0) ? C0 : (z == 1) ? C1 : C2;
    gemm_body<2>(Aa, Bb, bs, nullptr, Cc,
                 CC, CC, blockIdx.y * 128, blockIdx.x * 128, smem);
}

// ============================================================================
// K4: warp-per-position windowed attention + residual + LN2.
// ============================================================================
__global__ __launch_bounds__(256) void k_attn(
    const float* __restrict__ g2, const float* __restrict__ b2)
{
    int r    = blockIdx.x * 8 + (threadIdx.x >> 5);
    int lane = threadIdx.x & 31;
    int bb = r >> 11;
    int n  = r & (NN_ - 1);
    const float scale = 0.044194173824159216f;  // 512^-0.5

    size_t qb = (size_t)r * CC;
    int cA = 8 * lane;
    int cB = 256 + 8 * lane;

    __half2 qh[8];
    *(uint4*)&qh[0] = *(const uint4*)(g_Qpa + qb + cA);
    *(uint4*)&qh[4] = *(const uint4*)(g_Qpa + qb + cB);
    float qf[16];
#pragma unroll
    for (int i = 0; i < 8; i++) {
        float2 f = __half22float2(qh[i]);
        qf[2*i] = f.x; qf[2*i+1] = f.y;
    }

    bool   valid[KH];
    size_t nb[KH];
#pragma unroll
    for (int j = 0; j < KH; j++) {
        int nn = n + j - PAD;
        valid[j] = (nn >= 0) && (nn < NN_);
        nb[j] = valid[j] ? ((size_t)(bb * NN_ + nn)) * CC : 0;
    }

    float acc[KH];
#pragma unroll
    for (int j = 0; j < KH; j++) {
        float s = 0.f;
        if (valid[j]) {
            __half2 kh[8];
            *(uint4*)&kh[0] = *(const uint4*)(g_Kpa + nb[j] + cA);
            *(uint4*)&kh[4] = *(const uint4*)(g_Kpa + nb[j] + cB);
#pragma unroll
            for (int i = 0; i < 8; i++) {
                float2 f = __half22float2(kh[i]);
                s = fmaf(qf[2*i], f.x, s);
                s = fmaf(qf[2*i+1], f.y, s);
            }
        }
        acc[j] = s;
    }
#pragma unroll
    for (int j = 0; j < KH; j++) {
#pragma unroll
        for (int o = 16; o > 0; o >>= 1)
            acc[j] += __shfl_xor_sync(0xffffffffu, acc[j], o);
    }

    float m = acc[0];
#pragma unroll
    for (int j = 1; j < KH; j++) m = fmaxf(m, acc[j]);
    float wj[KH], es = 0.f;
#pragma unroll
    for (int j = 0; j < KH; j++) { wj[j] = expf(acc[j] - m); es += wj[j]; }
    float inv = scale / es;
#pragma unroll
    for (int j = 0; j < KH; j++) wj[j] *= inv;

    float attn[16];
#pragma unroll
    for (int i = 0; i < 16; i++) attn[i] = 0.f;
#pragma unroll
    for (int j = 0; j < KH; j++) {
        if (valid[j]) {
            __half2 vh[8];
            *(uint4*)&vh[0] = *(const uint4*)(g_Vpa + nb[j] + cA);
            *(uint4*)&vh[4] = *(const uint4*)(g_Vpa + nb[j] + cB);
            float w = wj[j];
#pragma unroll
            for (int i = 0; i < 8; i++) {
                float2 f = __half22float2(vh[i]);
                attn[2*i]   = fmaf(w, f.x, attn[2*i]);
                attn[2*i+1] = fmaf(w, f.y, attn[2*i+1]);
            }
        }
    }

    // residual (fp16 Qt) + LN2
    float x[16];
    {
        __half2 t0[4], t1[4];
        *(uint4*)&t0[0] = *(const uint4*)(g_Qth + qb + cA);
        *(uint4*)&t1[0] = *(const uint4*)(g_Qth + qb + cB);
#pragma unroll
        for (int i = 0; i < 4; i++) {
            float2 f0 = __half22float2(t0[i]);
            float2 f1 = __half22float2(t1[i]);
            x[2*i]      = f0.x + attn[2*i];
            x[2*i+1]    = f0.y + attn[2*i+1];
            x[8+2*i]    = f1.x + attn[8+2*i];
            x[8+2*i+1]  = f1.y + attn[8+2*i+1];
        }
    }
    // store X as fp16
    {
        __half2 xo[8];
#pragma unroll
        for (int i = 0; i < 8; i++)
            xo[i] = __floats2half2_rn(x[2*i], x[2*i+1]);
        *(uint4*)(g_Xh + qb + cA) = *(uint4*)&xo[0];
        *(uint4*)(g_Xh + qb + cB) = *(uint4*)&xo[4];
    }

    float xs = 0.f, xss = 0.f;
#pragma unroll
    for (int i = 0; i < 16; i++) { xs += x[i]; xss += x[i] * x[i]; }
#pragma unroll
    for (int o = 16; o > 0; o >>= 1) {
        xs  += __shfl_xor_sync(0xffffffffu, xs,  o);
        xss += __shfl_xor_sync(0xffffffffu, xss, o);
    }
    const float invC = 1.0f / CC;
    float mean = xs * invC;
    float rstd = rsqrtf(xss * invC - mean * mean + 1e-5f);

    float4 gA0 = *(const float4*)(g2 + cA);
    float4 gA1 = *(const float4*)(g2 + cA + 4);
    float4 gB0 = *(const float4*)(g2 + cB);
    float4 gB1 = *(const float4*)(g2 + cB + 4);
    float4 bA0 = *(const float4*)(b2 + cA);
    float4 bA1 = *(const float4*)(b2 + cA + 4);
    float4 bB0 = *(const float4*)(b2 + cB);
    float4 bB1 = *(const float4*)(b2 + cB + 4);
    float gg[16] = {gA0.x,gA0.y,gA0.z,gA0.w, gA1.x,gA1.y,gA1.z,gA1.w,
                    gB0.x,gB0.y,gB0.z,gB0.w, gB1.x,gB1.y,gB1.z,gB1.w};
    float bbv[16] = {bA0.x,bA0.y,bA0.z,bA0.w, bA1.x,bA1.y,bA1.z,bA1.w,
                     bB0.x,bB0.y,bB0.z,bB0.w, bB1.x,bB1.y,bB1.z,bB1.w};
    __half2 oh[8];
#pragma unroll
    for (int i = 0; i < 8; i++) {
        float v0 = (x[2*i]   - mean) * rstd * gg[2*i]   + bbv[2*i];
        float v1 = (x[2*i+1] - mean) * rstd * gg[2*i+1] + bbv[2*i+1];
        oh[i] = __floats2half2_rn(v0, v1);
    }
    *(uint4*)(g_L2a + qb + cA) = *(uint4*)&oh[0];
    *(uint4*)(g_L2a + qb + cB) = *(uint4*)&oh[4];
}

// ============================================================================
// weight prep
// ============================================================================
__global__ __launch_bounds__(256) void k_cvt(
    const float* __restrict__ src, __half* __restrict__ dst, int n)
{
    int i = blockIdx.x * 256 + threadIdx.x;
    if (i < n) dst[i] = __float2half_rn(src[i]);
}

// src [R, Cc] fp32 -> dst [Cc, R] fp16
__global__ void k_tcvt(const float* __restrict__ src,
                       __half* __restrict__ dst, int R, int Cc)
{
    __shared__ float t[32][33];
    int c0 = blockIdx.x * 32, r0 = blockIdx.y * 32;
    int tx = threadIdx.x, ty = threadIdx.y;
#pragma unroll
    for (int i = 0; i < 4; i++)
        t[ty + i * 8][tx] = src[(size_t)(r0 + ty + i * 8) * Cc + c0 + tx];
    __syncthreads();
#pragma unroll
    for (int i = 0; i < 4; i++) {
        float v = t[tx][ty + i * 8];
        dst[(size_t)(c0 + ty + i * 8) * R + r0 + tx] = __float2half_rn(v);
    }
}

// ============================================================================
extern "C" void kernel_launch(void* const* d_in, const int* in_sizes, int n_in,
                              void* d_out, int out_size)
{
    const float* query = (const float*)d_in[0];
    const float* key   = (const float*)d_in[1];
    const float* qe    = (const float*)d_in[2];
    const float* ke    = (const float*)d_in[3];
    const float* wq    = (const float*)d_in[4];
    const float* bq    = (const float*)d_in[5];
    const float* wk    = (const float*)d_in[6];
    const float* bk    = (const float*)d_in[7];
    const float* wv    = (const float*)d_in[8];
    const float* bv    = (const float*)d_in[9];
    const float* gn    = (const float*)d_in[10];
    const float* bn    = (const float*)d_in[11];
    const float* g2    = (const float*)d_in[12];
    const float* b2    = (const float*)d_in[13];
    const float* w1    = (const float*)d_in[14];
    const float* b1    = (const float*)d_in[15];
    const float* w2    = (const float*)d_in[16];
    const float* b2b   = (const float*)d_in[17];
    float* out = (float*)d_out;

    __half *Qa, *Ka, *Va, *Qpa, *Kpa, *Vpa, *L2a, *Ha;
    __half *wqd, *wkd, *wvd, *w1d, *w2d;
    cudaGetSymbolAddress((void**)&Qa,  g_Qa);
    cudaGetSymbolAddress((void**)&Ka,  g_Ka);
    cudaGetSymbolAddress((void**)&Va,  g_Va);
    cudaGetSymbolAddress((void**)&Qpa, g_Qpa);
    cudaGetSymbolAddress((void**)&Kpa, g_Kpa);
    cudaGetSymbolAddress((void**)&Vpa, g_Vpa);
    cudaGetSymbolAddress((void**)&L2a, g_L2a);
    cudaGetSymbolAddress((void**)&Ha,  g_Ha);
    cudaGetSymbolAddress((void**)&wqd, g_wq);
    cudaGetSymbolAddress((void**)&wkd, g_wk);
    cudaGetSymbolAddress((void**)&wvd, g_wv);
    cudaGetSymbolAddress((void**)&w1d, g_w1);
    cudaGetSymbolAddress((void**)&w2d, g_w2);

    cudaFuncSetAttribute(mma_gemm<1>,  cudaFuncAttributeMaxDynamicSharedMemorySize, GEMM_SMEM);
    cudaFuncSetAttribute(mma_gemm<3>,  cudaFuncAttributeMaxDynamicSharedMemorySize, GEMM_SMEM);
    cudaFuncSetAttribute(mma_gemm_proj, cudaFuncAttributeMaxDynamicSharedMemorySize, GEMM_SMEM);

    // weight prep
    k_cvt<<<(CC * CC + 255) / 256, 256>>>(wq, wqd, CC * CC);
    k_cvt<<<(CC * CC + 255) / 256, 256>>>(wk, wkd, CC * CC);
    k_cvt<<<(CC * CC + 255) / 256, 256>>>(wv, wvd, CC * CC);
    k_tcvt<<<dim3(MLPH / 32, CC / 32), dim3(32, 8)>>>(w1, w1d, CC, MLPH);
    k_tcvt<<<dim3(CC / 32, MLPH / 32), dim3(32, 8)>>>(w2, w2d, MLPH, CC);

    // 1) LN stats + transpose-convert
    k_stats<<<dim3(NN_ / 32, BB), 256>>>(query, key, qe, ke);
    k_cvtT<<<dim3(NN_ / 32, CC / 32, BB), dim3(32, 8)>>>(query, key, qe, ke, gn, bn);

    // 2) projections (merged NT GEMMs, K=512) -> fp16
    {
        dim3 g(CC / 128, RR / 128, 3);
        mma_gemm_proj<<<g, 256, GEMM_SMEM>>>(
            Qa, Ka, Va, wqd, wkd, wvd,
            bq, bk, bv, Qpa, Kpa, Vpa);
    }

    // 3) attention + residual + LN2 (warp per position)
    k_attn<<<RR / 8, 256>>>(g2, b2);

    // 4) MLP1: H = gelu(L2 @ w1^T + b1)   Nd=2048, K=512
    {
        dim3 g(MLPH / 128, RR / 128);
        mma_gemm<1><<<g, 256, GEMM_SMEM>>>(L2a, w1d, b1, nullptr, Ha, MLPH, CC);
    }
    // 5) out = transpose(X + H @ w2^T + b2b)   Nd=512, K=2048
    //    (residual + transpose fused into epilogue; writes final output)
    {
        dim3 g(CC / 128, RR / 128);
        mma_gemm<3><<<g, 256, GEMM_SMEM>>>(Ha, w2d, b2b, out, nullptr, CC, MLPH);
    }
}